// round 7
// baseline (speedup 1.0000x reference)
#include <cuda_runtime.h>

typedef unsigned long long ull;

constexpr int BS = 16384, D = 100, H = 16, P = 2;
constexpr int TB_B = 32;      // batch per block (8 warps x 4 b)
constexpr int TB_T = 8;       // t per block
constexpr int NTH  = 256;     // 8 warps
constexpr int JP   = 104;     // padded j / t extent in g_W0T
constexpr int W0S  = 1604;    // sW0 row stride in floats (401 float4: 400 data + 1 pad)
constexpr int W1S  = 260;

// smem map (float offsets)
constexpr int OFF_W0 = 0;                       // 8 * 1604 = 12832
constexpr int OFF_W1 = OFF_W0 + 8 * W0S;        // 12832 ; 8*260 = 2080
constexpr int OFF_B1 = OFF_W1 + 8 * W1S;        // 14912 ; 8*17 + pad = 144
constexpr int OFF_W2 = OFF_B1 + 144;            // 15056 ; 8*36 = 288
constexpr int OFF_B2 = OFF_W2 + 8 * 36;         // 15344 ; 16
constexpr int SMEM_FLOATS = OFF_B2 + 16;        // 15360 -> 61440 B (x3 CTA = 184320)

__device__ float g_W0T[JP * JP * H];  // [t][j][i], zero-padded t,j >= 100
__device__ float g_xT[D * BS];        // [j][b]

__global__ void transpose_w0_kernel(const float* __restrict__ W0) {
    int t = blockIdx.x;  // 0..103
    for (int e = threadIdx.x; e < JP * H; e += blockDim.x) {
        int j = e >> 4, i = e & 15;
        float v = (t < D && j < D) ? W0[(t * H + i) * D + j] : 0.f;
        g_W0T[t * (JP * H) + e] = v;
    }
}

__global__ void transpose_x_kernel(const float* __restrict__ x) {
    __shared__ float tile[32][33];
    int bb = blockIdx.x * 32, jb = blockIdx.y * 32;
    int tx = threadIdx.x, ty = threadIdx.y;
    for (int r = ty; r < 32; r += 8) {
        int j = jb + tx;
        tile[r][tx] = (j < D) ? x[(bb + r) * D + j] : 0.f;
    }
    __syncthreads();
    for (int r = ty; r < 32; r += 8) {
        int j = jb + r;
        if (j < D) g_xT[j * BS + bb + tx] = tile[tx][r];
    }
}

__device__ __forceinline__ ull pk2(float a, float b) {
    ull r; asm("mov.b64 %0, {%1, %2};" : "=l"(r) : "f"(a), "f"(b)); return r;
}
__device__ __forceinline__ void unpk2(ull v, float& a, float& b) {
    asm("mov.b64 {%0, %1}, %2;" : "=f"(a), "=f"(b) : "l"(v));
}
__device__ __forceinline__ ull ffma2(ull a, ull b, ull c) {
    ull d; asm("fma.rn.f32x2 %0, %1, %2, %3;" : "=l"(d) : "l"(a), "l"(b), "l"(c));
    return d;
}
__device__ __forceinline__ float lrelu(float v) { return v > 0.f ? v : 0.01f * v; }

__global__ void __launch_bounds__(NTH, 3)
mlp_kernel(const float* __restrict__ M, const float* __restrict__ W1g,
           const float* __restrict__ W2g, const float* __restrict__ b0g,
           const float* __restrict__ b1g, const float* __restrict__ b2g,
           float* __restrict__ out) {
    extern __shared__ float smem[];
    float* sW0 = smem + OFF_W0;
    float* sW1 = smem + OFF_W1;
    float* sB1 = smem + OFF_B1;
    float* sW2 = smem + OFF_W2;
    float* sB2 = smem + OFF_B2;

    const int tid  = threadIdx.x;
    const int lane = tid & 31, w = tid >> 5;
    const int tl = lane & 7, bq = lane >> 3;
    const int t0 = blockIdx.y * TB_T;
    const int t  = t0 + tl;
    const bool tv = (t < D);
    const int tc = tv ? t : (D - 1);          // clamp: invalid lanes read valid dup
    const int Bb    = blockIdx.x * TB_B;
    const int Bbase = Bb + w * 4 + bq;        // this thread's single b

    // ---- stage W0 (j<100 only; stride 401 f4 matches 400 data + 1 pad) ----
    for (int e = tid; e < 8 * 400; e += NTH) {
        int r = e / 400, c = e - r * 400;
        float4 v = *((const float4*)(g_W0T + (t0 + r) * (JP * H)) + c);
        ((float4*)(sW0 + r * W0S))[c] = v;
    }
    for (int e = tid; e < 8 * 256; e += NTH) {               // W1: DIRECT copy
        int r = e >> 8, c = e & 255;
        sW1[r * W1S + c] = (t0 + r < D) ? W1g[(t0 + r) * 256 + c] : 0.f;
    }
    if (tid < 128) {
        int r = tid >> 4, c = tid & 15;
        sB1[r * 17 + c] = (t0 + r < D) ? b1g[(t0 + r) * H + c] : 0.f;
    }
    if (tid < 256) {
        int r = tid >> 5, c = tid & 31;
        sW2[r * 36 + c] = (t0 + r < D) ? W2g[(t0 + r) * (P * H) + c] : 0.f;
    }
    if (tid < 16) {
        int r = tid >> 1, c = tid & 1;
        sB2[r * 2 + c] = (t0 + r < D) ? b2g[(t0 + r) * P + c] : 0.f;
    }
    __syncthreads();

    // ---- acc init with b0 ----
    ull acc[8];
#pragma unroll
    for (int ip = 0; ip < 8; ++ip) {
        float a = tv ? __ldg(b0g + t * H + 2 * ip)     : 0.f;
        float b = tv ? __ldg(b0g + t * H + 2 * ip + 1) : 0.f;
        acc[ip] = pk2(a, b);
    }

    const float* mp = M + (size_t)Bbase * (D * D) + tc;  // + j*D
    const float* xp = g_xT + Bbase;                      // + j*BS

    // 3-buffer register pipeline, chunk = 4 j, prefetch distance = 2 chunks
    float m[3][4], xv[3][4];

#define LOAD_CHUNK(cn, buf)                                                     \
    if ((cn) < 25) {                                                            \
        _Pragma("unroll")                                                       \
        for (int u = 0; u < 4; ++u) {                                           \
            int j = (cn) * 4 + u;                                               \
            m[buf][u]  = __ldg(mp + j * D);                                     \
            xv[buf][u] = __ldg(xp + (size_t)j * BS);                            \
        }                                                                       \
    }

#define COMP_CHUNK(cn, buf)                                                     \
    {                                                                           \
        _Pragma("unroll")                                                       \
        for (int u = 0; u < 4; ++u) {                                           \
            int j = (cn) * 4 + u;                                               \
            const longlong2* wr = (const longlong2*)(sW0 + tl * W0S + j * 16);  \
            longlong2 q0 = wr[0], q1 = wr[1], q2 = wr[2], q3 = wr[3];           \
            ull W[8] = {(ull)q0.x, (ull)q0.y, (ull)q1.x, (ull)q1.y,             \
                        (ull)q2.x, (ull)q2.y, (ull)q3.x, (ull)q3.y};            \
            float mx = m[buf][u] * xv[buf][u];                                  \
            ull p = pk2(mx, mx);                                                \
            _Pragma("unroll")                                                   \
            for (int ip = 0; ip < 8; ++ip) acc[ip] = ffma2(W[ip], p, acc[ip]);  \
        }                                                                       \
    }

    LOAD_CHUNK(0, 0);
    LOAD_CHUNK(1, 1);
#pragma unroll 1
    for (int kb = 0; kb < 24; kb += 3) {
        LOAD_CHUNK(kb + 2, 2); COMP_CHUNK(kb, 0);
        LOAD_CHUNK(kb + 3, 0); COMP_CHUNK(kb + 1, 1);
        LOAD_CHUNK(kb + 4, 1); COMP_CHUNK(kb + 2, 2);
    }
    COMP_CHUNK(24, 0);
#undef LOAD_CHUNK
#undef COMP_CHUNK

    // ---- diagonal correction: subtract j == t term ----
    if (tv) {
        float md = __ldg(M + ((size_t)Bbase * D + t) * D + t);
        float mx = md * __ldg(xp + (size_t)t * BS);
        ull pm = pk2(-mx, -mx);
        const longlong2* wr = (const longlong2*)(sW0 + tl * W0S + t * 16);
        longlong2 q0 = wr[0], q1 = wr[1], q2 = wr[2], q3 = wr[3];
        ull W[8] = {(ull)q0.x, (ull)q0.y, (ull)q1.x, (ull)q1.y,
                    (ull)q2.x, (ull)q2.y, (ull)q3.x, (ull)q3.y};
#pragma unroll
        for (int ip = 0; ip < 8; ++ip) acc[ip] = ffma2(W[ip], pm, acc[ip]);
    }

    // ---- layers 1 & 2 ----
    float h0f[16];
#pragma unroll
    for (int ip = 0; ip < 8; ++ip) {
        float a, b; unpk2(acc[ip], a, b);
        h0f[2 * ip]     = lrelu(a);
        h0f[2 * ip + 1] = lrelu(b);
    }
    float h1[16];
#pragma unroll
    for (int ii = 0; ii < 16; ++ii) {
        const float4* w1r = (const float4*)(sW1 + tl * W1S + ii * 16);
        float4 a = w1r[0], b = w1r[1], c = w1r[2], d = w1r[3];
        float s = sB1[tl * 17 + ii];
        s = fmaf(a.x, h0f[0],  s); s = fmaf(a.y, h0f[1],  s);
        s = fmaf(a.z, h0f[2],  s); s = fmaf(a.w, h0f[3],  s);
        s = fmaf(b.x, h0f[4],  s); s = fmaf(b.y, h0f[5],  s);
        s = fmaf(b.z, h0f[6],  s); s = fmaf(b.w, h0f[7],  s);
        s = fmaf(c.x, h0f[8],  s); s = fmaf(c.y, h0f[9],  s);
        s = fmaf(c.z, h0f[10], s); s = fmaf(c.w, h0f[11], s);
        s = fmaf(d.x, h0f[12], s); s = fmaf(d.y, h0f[13], s);
        s = fmaf(d.z, h0f[14], s); s = fmaf(d.w, h0f[15], s);
        h1[ii] = lrelu(s);
    }
    float po[2];
#pragma unroll
    for (int p = 0; p < 2; ++p) {
        const float4* w2r = (const float4*)(sW2 + tl * 36 + p * 16);
        float4 a = w2r[0], b = w2r[1], c = w2r[2], d = w2r[3];
        float s = sB2[tl * 2 + p];
        s = fmaf(a.x, h1[0],  s); s = fmaf(a.y, h1[1],  s);
        s = fmaf(a.z, h1[2],  s); s = fmaf(a.w, h1[3],  s);
        s = fmaf(b.x, h1[4],  s); s = fmaf(b.y, h1[5],  s);
        s = fmaf(b.z, h1[6],  s); s = fmaf(b.w, h1[7],  s);
        s = fmaf(c.x, h1[8],  s); s = fmaf(c.y, h1[9],  s);
        s = fmaf(c.z, h1[10], s); s = fmaf(c.w, h1[11], s);
        s = fmaf(d.x, h1[12], s); s = fmaf(d.y, h1[13], s);
        s = fmaf(d.z, h1[14], s); s = fmaf(d.w, h1[15], s);
        po[p] = s;
    }
    if (tv) {
        float2 o = make_float2(po[0], po[1]);
        *(float2*)(out + ((size_t)Bbase * D + t) * P) = o;
    }
}

extern "C" void kernel_launch(void* const* d_in, const int* in_sizes, int n_in,
                              void* d_out, int out_size) {
    const float* x  = (const float*)d_in[0];
    const float* M  = (const float*)d_in[1];
    const float* W0 = (const float*)d_in[2];
    const float* W1 = (const float*)d_in[3];
    const float* W2 = (const float*)d_in[4];
    const float* b0 = (const float*)d_in[5];
    const float* b1 = (const float*)d_in[6];
    const float* b2 = (const float*)d_in[7];
    float* out = (float*)d_out;

    constexpr int SMEM_BYTES = SMEM_FLOATS * 4;
    cudaFuncSetAttribute(mlp_kernel, cudaFuncAttributeMaxDynamicSharedMemorySize,
                         SMEM_BYTES);

    transpose_w0_kernel<<<JP, 256>>>(W0);
    transpose_x_kernel<<<dim3(BS / 32, (D + 31) / 32), dim3(32, 8)>>>(x);

    dim3 grid(BS / TB_B, (D + TB_T - 1) / TB_T);   // 512 x 13
    mlp_kernel<<<grid, NTH, SMEM_BYTES>>>(M, W1, W2, b0, b1, b2, out);
}

// round 11
// speedup vs baseline: 1.0866x; 1.0866x over previous
#include <cuda_runtime.h>

typedef unsigned long long ull;

constexpr int BS = 16384, D = 100, H = 16, P = 2;
constexpr int TB_B = 128;     // batch per block (8 warps x 4 bq x 4 b)
constexpr int TB_T = 8;       // t per block
constexpr int NTH  = 256;     // 8 warps
constexpr int JP   = 104;     // padded t extent in g_W0T
constexpr int W0S  = 1604;    // sW0 row stride floats (401 f4: 400 data + 1 pad)
constexpr int W1S  = 260;

// smem map (float offsets)
constexpr int OFF_W0 = 0;                       // 8*1604 = 12832
constexpr int OFF_W1 = OFF_W0 + 8 * W0S;        // 12832 ; 2080
constexpr int OFF_B1 = OFF_W1 + 8 * W1S;        // 14912 ; 144
constexpr int OFF_W2 = OFF_B1 + 144;            // 15056 ; 288
constexpr int OFF_B2 = OFF_W2 + 8 * 36;         // 15344 ; 16
constexpr int SMEM_FLOATS = OFF_B2 + 16;        // 15360 -> 61440 B

__device__ float g_W0T[JP * D * H];   // [t][j][i], zero-padded t >= 100
__device__ float g_xT[D * BS];        // [j][b]

__global__ void transpose_w0_kernel(const float* __restrict__ W0) {
    int t = blockIdx.x;  // 0..103
    for (int e = threadIdx.x; e < D * H; e += blockDim.x) {
        int j = e >> 4, i = e & 15;
        float v = (t < D) ? W0[(t * H + i) * D + j] : 0.f;
        g_W0T[t * (D * H) + e] = v;
    }
}

__global__ void transpose_x_kernel(const float* __restrict__ x) {
    __shared__ float tile[32][33];
    int bb = blockIdx.x * 32, jb = blockIdx.y * 32;
    int tx = threadIdx.x, ty = threadIdx.y;
    for (int r = ty; r < 32; r += 8) {
        int j = jb + tx;
        tile[r][tx] = (j < D) ? x[(bb + r) * D + j] : 0.f;
    }
    __syncthreads();
    for (int r = ty; r < 32; r += 8) {
        int j = jb + r;
        if (j < D) g_xT[j * BS + bb + tx] = tile[tx][r];
    }
}

__device__ __forceinline__ ull pk2(float a, float b) {
    ull r; asm("mov.b64 %0, {%1, %2};" : "=l"(r) : "f"(a), "f"(b)); return r;
}
__device__ __forceinline__ void unpk2(ull v, float& a, float& b) {
    asm("mov.b64 {%0, %1}, %2;" : "=f"(a), "=f"(b) : "l"(v));
}
__device__ __forceinline__ ull ffma2(ull a, ull b, ull c) {
    ull d; asm("fma.rn.f32x2 %0, %1, %2, %3;" : "=l"(d) : "l"(a), "l"(b), "l"(c));
    return d;
}
__device__ __forceinline__ float lrelu(float v) { return v > 0.f ? v : 0.01f * v; }

__global__ void __launch_bounds__(NTH, 2)
mlp_kernel(const float* __restrict__ M, const float* __restrict__ W1g,
           const float* __restrict__ W2g, const float* __restrict__ b0g,
           const float* __restrict__ b1g, const float* __restrict__ b2g,
           float* __restrict__ out) {
    extern __shared__ float smem[];
    float* sW0 = smem + OFF_W0;
    float* sW1 = smem + OFF_W1;
    float* sB1 = smem + OFF_B1;
    float* sW2 = smem + OFF_W2;
    float* sB2 = smem + OFF_B2;

    const int tid  = threadIdx.x;
    const int lane = tid & 31, w = tid >> 5;
    const int tl = lane & 7, bq = (lane >> 3) & 3;
    const int t0 = blockIdx.x * TB_T;          // t-tiles on FAST grid dim (L2 reuse)
    const int t  = t0 + tl;
    const bool tv = (t < D);
    const int tc = tv ? t : (D - 1);
    const int Bb    = blockIdx.y * TB_B;
    const int Bbase = Bb + w * 16 + bq * 4;    // this thread: b = Bbase .. Bbase+3

    // ---- stage W0 / W1 / b1 / W2 / b2 ----
    for (int e = tid; e < 8 * 400; e += NTH) {               // W0: 8 rows x 400 f4
        int r = e / 400, c = e - r * 400;
        float4 v = *((const float4*)(g_W0T + (t0 + r) * (D * H)) + c);
        ((float4*)(sW0 + r * W0S))[c] = v;
    }
    for (int e = tid; e < 8 * 256; e += NTH) {               // W1: DIRECT copy
        int r = e >> 8, c = e & 255;
        sW1[r * W1S + c] = (t0 + r < D) ? W1g[(t0 + r) * 256 + c] : 0.f;
    }
    if (tid < 128) {
        int r = tid >> 4, c = tid & 15;
        sB1[r * 17 + c] = (t0 + r < D) ? b1g[(t0 + r) * H + c] : 0.f;
    }
    if (tid < 256) {
        int r = tid >> 5, c = tid & 31;
        sW2[r * 36 + c] = (t0 + r < D) ? W2g[(t0 + r) * (P * H) + c] : 0.f;
    }
    if (tid < 16) {
        int r = tid >> 1, c = tid & 1;
        sB2[r * 2 + c] = (t0 + r < D) ? b2g[(t0 + r) * P + c] : 0.f;
    }
    __syncthreads();

    // ---- acc init with b0 (acc[u][ip]: u = local b, ip = i-pair) ----
    ull acc[4][8];
#pragma unroll
    for (int ip = 0; ip < 8; ++ip) {
        float a = tv ? __ldg(b0g + t * H + 2 * ip)     : 0.f;
        float b = tv ? __ldg(b0g + t * H + 2 * ip + 1) : 0.f;
        ull bb = pk2(a, b);
        acc[0][ip] = bb; acc[1][ip] = bb; acc[2][ip] = bb; acc[3][ip] = bb;
    }

    const float* mp = M + (size_t)Bbase * (D * D) + tc;  // + j*D + u*D*D
    const float* xp = g_xT + Bbase;                      // + j*BS

    // 2-buffer register pipeline: chunk = 2 j
    float  m[2][2][4];
    float4 xv[2][2];

#define LOAD_CHUNK(cn, buf)                                                     \
    if ((cn) < 50) {                                                            \
        _Pragma("unroll")                                                       \
        for (int jj = 0; jj < 2; ++jj) {                                        \
            int j = (cn) * 2 + jj;                                              \
            m[buf][jj][0] = __ldg(mp + j * D);                                  \
            m[buf][jj][1] = __ldg(mp + j * D + D * D);                          \
            m[buf][jj][2] = __ldg(mp + j * D + 2 * D * D);                      \
            m[buf][jj][3] = __ldg(mp + j * D + 3 * D * D);                      \
            xv[buf][jj] = *(const float4*)(xp + (size_t)j * BS);                \
        }                                                                       \
    }

#define COMP_CHUNK(cn, buf)                                                     \
    {                                                                           \
        _Pragma("unroll")                                                       \
        for (int jj = 0; jj < 2; ++jj) {                                        \
            int j = (cn) * 2 + jj;                                              \
            const longlong2* wr = (const longlong2*)(sW0 + tl * W0S + j * 16);  \
            longlong2 q0 = wr[0], q1 = wr[1], q2 = wr[2], q3 = wr[3];           \
            ull W[8] = {(ull)q0.x, (ull)q0.y, (ull)q1.x, (ull)q1.y,             \
                        (ull)q2.x, (ull)q2.y, (ull)q3.x, (ull)q3.y};            \
            float mx0 = m[buf][jj][0] * xv[buf][jj].x;                          \
            float mx1 = m[buf][jj][1] * xv[buf][jj].y;                          \
            float mx2 = m[buf][jj][2] * xv[buf][jj].z;                          \
            float mx3 = m[buf][jj][3] * xv[buf][jj].w;                          \
            ull p0 = pk2(mx0, mx0), p1 = pk2(mx1, mx1);                         \
            ull p2 = pk2(mx2, mx2), p3 = pk2(mx3, mx3);                         \
            _Pragma("unroll")                                                   \
            for (int ip = 0; ip < 8; ++ip) {                                    \
                acc[0][ip] = ffma2(W[ip], p0, acc[0][ip]);                      \
                acc[1][ip] = ffma2(W[ip], p1, acc[1][ip]);                      \
                acc[2][ip] = ffma2(W[ip], p2, acc[2][ip]);                      \
                acc[3][ip] = ffma2(W[ip], p3, acc[3][ip]);                      \
            }                                                                   \
        }                                                                       \
    }

    LOAD_CHUNK(0, 0);
#pragma unroll 1
    for (int cn = 0; cn < 48; cn += 2) {
        LOAD_CHUNK(cn + 1, 1);
        COMP_CHUNK(cn, 0);
        LOAD_CHUNK(cn + 2, 0);
        COMP_CHUNK(cn + 1, 1);
    }
    LOAD_CHUNK(49, 1);
    COMP_CHUNK(48, 0);
    COMP_CHUNK(49, 1);
#undef LOAD_CHUNK
#undef COMP_CHUNK

    // ---- diagonal correction: subtract j == t term ----
    if (tv) {
        float4 xd = *(const float4*)(g_xT + (size_t)t * BS + Bbase);
        const float xdv[4] = {xd.x, xd.y, xd.z, xd.w};
        const longlong2* wr = (const longlong2*)(sW0 + tl * W0S + t * 16);
        longlong2 q0 = wr[0], q1 = wr[1], q2 = wr[2], q3 = wr[3];
        ull W[8] = {(ull)q0.x, (ull)q0.y, (ull)q1.x, (ull)q1.y,
                    (ull)q2.x, (ull)q2.y, (ull)q3.x, (ull)q3.y};
#pragma unroll
        for (int u = 0; u < 4; ++u) {
            float md = __ldg(M + (size_t)(Bbase + u) * (D * D) + t * D + t);
            float mx = md * xdv[u];
            ull pm = pk2(-mx, -mx);
#pragma unroll
            for (int ip = 0; ip < 8; ++ip) acc[u][ip] = ffma2(W[ip], pm, acc[u][ip]);
        }
    }

    // ---- layers 1 & 2 per owned b ----
#pragma unroll 1
    for (int u = 0; u < 4; ++u) {
        float h0f[16];
#pragma unroll
        for (int ip = 0; ip < 8; ++ip) {
            float a, b; unpk2(acc[u][ip], a, b);
            h0f[2 * ip]     = lrelu(a);
            h0f[2 * ip + 1] = lrelu(b);
        }
        float h1[16];
#pragma unroll
        for (int ii = 0; ii < 16; ++ii) {
            const float4* w1r = (const float4*)(sW1 + tl * W1S + ii * 16);
            float4 a = w1r[0], b = w1r[1], c = w1r[2], d = w1r[3];
            float s = sB1[tl * 17 + ii];
            s = fmaf(a.x, h0f[0],  s); s = fmaf(a.y, h0f[1],  s);
            s = fmaf(a.z, h0f[2],  s); s = fmaf(a.w, h0f[3],  s);
            s = fmaf(b.x, h0f[4],  s); s = fmaf(b.y, h0f[5],  s);
            s = fmaf(b.z, h0f[6],  s); s = fmaf(b.w, h0f[7],  s);
            s = fmaf(c.x, h0f[8],  s); s = fmaf(c.y, h0f[9],  s);
            s = fmaf(c.z, h0f[10], s); s = fmaf(c.w, h0f[11], s);
            s = fmaf(d.x, h0f[12], s); s = fmaf(d.y, h0f[13], s);
            s = fmaf(d.z, h0f[14], s); s = fmaf(d.w, h0f[15], s);
            h1[ii] = lrelu(s);
        }
        float po[2];
#pragma unroll
        for (int p = 0; p < 2; ++p) {
            const float4* w2r = (const float4*)(sW2 + tl * 36 + p * 16);
            float4 a = w2r[0], b = w2r[1], c = w2r[2], d = w2r[3];
            float s = sB2[tl * 2 + p];
            s = fmaf(a.x, h1[0],  s); s = fmaf(a.y, h1[1],  s);
            s = fmaf(a.z, h1[2],  s); s = fmaf(a.w, h1[3],  s);
            s = fmaf(b.x, h1[4],  s); s = fmaf(b.y, h1[5],  s);
            s = fmaf(b.z, h1[6],  s); s = fmaf(b.w, h1[7],  s);
            s = fmaf(c.x, h1[8],  s); s = fmaf(c.y, h1[9],  s);
            s = fmaf(c.z, h1[10], s); s = fmaf(c.w, h1[11], s);
            s = fmaf(d.x, h1[12], s); s = fmaf(d.y, h1[13], s);
            s = fmaf(d.z, h1[14], s); s = fmaf(d.w, h1[15], s);
            po[p] = s;
        }
        if (tv) {
            float2 o = make_float2(po[0], po[1]);
            *(float2*)(out + ((size_t)(Bbase + u) * D + t) * P) = o;
        }
    }
}

extern "C" void kernel_launch(void* const* d_in, const int* in_sizes, int n_in,
                              void* d_out, int out_size) {
    const float* x  = (const float*)d_in[0];
    const float* M  = (const float*)d_in[1];
    const float* W0 = (const float*)d_in[2];
    const float* W1 = (const float*)d_in[3];
    const float* W2 = (const float*)d_in[4];
    const float* b0 = (const float*)d_in[5];
    const float* b1 = (const float*)d_in[6];
    const float* b2 = (const float*)d_in[7];
    float* out = (float*)d_out;

    constexpr int SMEM_BYTES = SMEM_FLOATS * 4;
    cudaFuncSetAttribute(mlp_kernel, cudaFuncAttributeMaxDynamicSharedMemorySize,
                         SMEM_BYTES);

    transpose_w0_kernel<<<JP, 256>>>(W0);
    transpose_x_kernel<<<dim3(BS / 32, (D + 31) / 32), dim3(32, 8)>>>(x);

    // t-tiles on grid.x (fast dim): the 13 t-blocks sharing M cache lines are
    // consecutive bids -> co-resident -> each M line fetched from DRAM once.
    dim3 grid((D + TB_T - 1) / TB_T, BS / TB_B);   // 13 x 128
    mlp_kernel<<<grid, NTH, SMEM_BYTES>>>(M, W1, W2, b0, b1, b2, out);
}